// round 16
// baseline (speedup 1.0000x reference)
#include <cuda_runtime.h>
#include <cuda_bf16.h>
#include <cstdint>
#include <math.h>

// Problem: B=64, S=1024, I=256, H=256, G=3H=768, two GRU layers.
#define PB 64
#define PS 1024
#define PH 256
#define PG 768
#define BSH (PB * PS * PH)   // 16,777,216

typedef unsigned long long ull;

// Scratch (device globals: the sanctioned no-alloc workaround)
__device__ float g_xg[(size_t)PB * PS * PG];  // per-layer input projections [B,S,768]
__device__ float g_h1[(size_t)PB * PS * PH];  // layer-0 hidden states [B,S,256]
__device__ __align__(16) __nv_bfloat16 g_Ahi[(size_t)PB * PS * PH];  // A bf16 hi
__device__ __align__(16) __nv_bfloat16 g_Alo[(size_t)PB * PS * PH];  // A bf16 lo
__device__ __align__(16) __nv_bfloat16 g_Whi[PG * PH];               // W bf16 hi
__device__ __align__(16) __nv_bfloat16 g_Wlo[PG * PH];               // W bf16 lo

// ---- f32x2 packed helpers (PTX-only path) ----
__device__ __forceinline__ void fma2(ull& d, ull a, ull b) {
    asm("fma.rn.f32x2 %0, %1, %2, %0;" : "+l"(d) : "l"(a), "l"(b));
}
__device__ __forceinline__ float2 unpack2(ull v) {
    float lo, hi;
    asm("mov.b64 {%0, %1}, %2;" : "=f"(lo), "=f"(hi) : "l"(v));
    return make_float2(lo, hi);
}
__device__ __forceinline__ uint32_t smem_u32(const void* p) {
    uint32_t a;
    asm("{ .reg .u64 t; cvta.to.shared.u64 t, %1; cvt.u32.u64 %0, t; }"
        : "=r"(a) : "l"(p));
    return a;
}
__device__ __forceinline__ float tanh_ap(float x) {
    float y;
    asm("tanh.approx.f32 %0, %1;" : "=f"(y) : "f"(x));
    return y;
}
__device__ __forceinline__ void st_async_f32(uint32_t laddr, uint32_t lmbar,
                                             uint32_t rank, float v) {
    asm volatile(
        "{\n\t.reg .b32 ra, rm;\n\t"
        "mapa.shared::cluster.u32 ra, %0, %2;\n\t"
        "mapa.shared::cluster.u32 rm, %1, %2;\n\t"
        "st.async.shared::cluster.mbarrier::complete_tx::bytes.u32 [ra], %3, [rm];\n\t}"
        :: "r"(laddr), "r"(lmbar), "r"(rank), "r"(__float_as_uint(v)) : "memory");
}
__device__ __forceinline__ void mb_wait(uint32_t mbar, uint32_t phase) {
    uint32_t done;
    asm volatile(
        "{\n\t.reg .pred p;\n\t"
        "mbarrier.try_wait.parity.acquire.cluster.shared::cta.b64 p, [%1], %2, 0x989680;\n\t"
        "selp.b32 %0, 1, 0, p;\n\t}"
        : "=r"(done) : "r"(mbar), "r"(phase) : "memory");
    while (!done) {
        asm volatile(
            "{\n\t.reg .pred p;\n\t"
            "mbarrier.try_wait.parity.acquire.cluster.shared::cta.b64 p, [%1], %2, 0x989680;\n\t"
            "selp.b32 %0, 1, 0, p;\n\t}"
            : "=r"(done) : "r"(mbar), "r"(phase) : "memory");
    }
}
// ---- mma.sync bf16 helpers ----
__device__ __forceinline__ void ldsm_x4(uint32_t& r0, uint32_t& r1, uint32_t& r2,
                                        uint32_t& r3, uint32_t a) {
    asm volatile("ldmatrix.sync.aligned.m8n8.x4.shared.b16 {%0,%1,%2,%3}, [%4];"
                 : "=r"(r0), "=r"(r1), "=r"(r2), "=r"(r3) : "r"(a));
}
__device__ __forceinline__ void mma_bf16(float* c, const uint32_t* a, const uint32_t* b) {
    asm volatile(
        "mma.sync.aligned.m16n8k16.row.col.f32.bf16.bf16.f32 "
        "{%0,%1,%2,%3}, {%4,%5,%6,%7}, {%8,%9}, {%0,%1,%2,%3};"
        : "+f"(c[0]), "+f"(c[1]), "+f"(c[2]), "+f"(c[3])
        : "r"(a[0]), "r"(a[1]), "r"(a[2]), "r"(a[3]), "r"(b[0]), "r"(b[1]));
}

// ---------------------------------------------------------------------------
// Split fp32 -> bf16 hi + bf16 lo (residual). n4 = element_count / 4.
// ---------------------------------------------------------------------------
__global__ __launch_bounds__(256) void split2(
    const float* __restrict__ src, __nv_bfloat16* __restrict__ hi,
    __nv_bfloat16* __restrict__ lo, int n4)
{
    int i = blockIdx.x * blockDim.x + threadIdx.x;
    if (i >= n4) return;
    float4 v = reinterpret_cast<const float4*>(src)[i];
    __nv_bfloat162 h01 = __floats2bfloat162_rn(v.x, v.y);
    __nv_bfloat162 h23 = __floats2bfloat162_rn(v.z, v.w);
    __nv_bfloat162 l01 = __floats2bfloat162_rn(v.x - __bfloat162float(h01.x),
                                               v.y - __bfloat162float(h01.y));
    __nv_bfloat162 l23 = __floats2bfloat162_rn(v.z - __bfloat162float(h23.x),
                                               v.w - __bfloat162float(h23.y));
    reinterpret_cast<__nv_bfloat162*>(hi)[2 * i]     = h01;
    reinterpret_cast<__nv_bfloat162*>(hi)[2 * i + 1] = h23;
    reinterpret_cast<__nv_bfloat162*>(lo)[2 * i]     = l01;
    reinterpret_cast<__nv_bfloat162*>(lo)[2 * i + 1] = l23;
}

// ---------------------------------------------------------------------------
// Tensor-core GEMM: out[m][n] = sum_k A[m][k]*W[n][k] + bias[n], fp32-accurate
// via bf16 split 3-pass: Ahi*Whi + Alo*Whi + Ahi*Wlo.
// BM=128, BN=64, BK=32, 256 threads = 8 warps (4m x 2n), warp tile 32x32.
// B fragments: W is [n][k] k-contiguous == exactly the k16n8 "col" operand
// when loaded with NON-trans ldmatrix over rows=n (R15 bug: used .trans).
// ---------------------------------------------------------------------------
#define LDP 40   // padded row length in bf16

__global__ __launch_bounds__(256) void gemm_mma(
    const __nv_bfloat16* __restrict__ Ahi, const __nv_bfloat16* __restrict__ Alo,
    const __nv_bfloat16* __restrict__ Whi, const __nv_bfloat16* __restrict__ Wlo,
    const float* __restrict__ bias, float* __restrict__ out)
{
    __shared__ __align__(16) __nv_bfloat16 sAh[128 * LDP];
    __shared__ __align__(16) __nv_bfloat16 sAl[128 * LDP];
    __shared__ __align__(16) __nv_bfloat16 sWh[64 * LDP];
    __shared__ __align__(16) __nv_bfloat16 sWl[64 * LDP];

    const int t  = threadIdx.x;
    const int bn = blockIdx.x;    // 0..11
    const int bm = blockIdx.y;    // 0..511
    const int wq = t >> 5;
    const int l  = t & 31;
    const int wm = wq & 3;        // m-tile 0..3 (32 rows each)
    const int wn = wq >> 2;       // n-tile 0..1 (32 cols each)

    const int srow = t >> 2;      // 0..63 (staging row)
    const int chk  = t & 3;       // 0..3  (16B chunk along k)

    const uint32_t aHb = smem_u32(sAh), aLb = smem_u32(sAl);
    const uint32_t wHb = smem_u32(sWh), wLb = smem_u32(sWl);

    float acc[2][4][4];
#pragma unroll
    for (int i = 0; i < 2; i++)
#pragma unroll
        for (int j = 0; j < 4; j++)
#pragma unroll
            for (int k = 0; k < 4; k++) acc[i][j][k] = 0.f;

    // ldmatrix lane-address components
    // A x4: lanes map to (row within 16, k-half) giving frags a0..a3 in PTX order.
    const int a_rl  = ((l >> 3) & 1) * 8 + (l & 7);   // row = lane % 16
    const int a_cl  = (l >> 4) * 16;                  // k-half byte offset
    // B x4 (non-trans): m0 = n-blk0/k0-7, m1 = n-blk0/k8-15, m2 = n-blk1/k0-7,
    // m3 = n-blk1/k8-15.
    const int b_rl  = ((l >> 4) & 1) * 8 + (l & 7);   // n row within 16
    const int b_cl  = ((l >> 3) & 1) * 16;            // k-half byte offset

    for (int kt = 0; kt < 256; kt += 32) {
        // ---- stage hi/lo tiles ----
#pragma unroll
        for (int r = 0; r < 2; r++) {
            int row = srow + r * 64;
            size_t g = (size_t)(bm * 128 + row) * 256 + kt + chk * 8;
            *reinterpret_cast<uint4*>(&sAh[row * LDP + chk * 8]) =
                *reinterpret_cast<const uint4*>(&Ahi[g]);
            *reinterpret_cast<uint4*>(&sAl[row * LDP + chk * 8]) =
                *reinterpret_cast<const uint4*>(&Alo[g]);
        }
        {
            size_t g = (size_t)(bn * 64 + srow) * 256 + kt + chk * 8;
            *reinterpret_cast<uint4*>(&sWh[srow * LDP + chk * 8]) =
                *reinterpret_cast<const uint4*>(&Whi[g]);
            *reinterpret_cast<uint4*>(&sWl[srow * LDP + chk * 8]) =
                *reinterpret_cast<const uint4*>(&Wlo[g]);
        }
        __syncthreads();

#pragma unroll
        for (int ks = 0; ks < 2; ks++) {
            uint32_t ah[2][4], al[2][4], bh[4][2], bl[4][2];
#pragma unroll
            for (int hm = 0; hm < 2; hm++) {
                uint32_t off = (uint32_t)((wm * 32 + hm * 16 + a_rl) * (LDP * 2)
                                          + ks * 32 + a_cl);
                ldsm_x4(ah[hm][0], ah[hm][1], ah[hm][2], ah[hm][3], aHb + off);
                ldsm_x4(al[hm][0], al[hm][1], al[hm][2], al[hm][3], aLb + off);
            }
#pragma unroll
            for (int g = 0; g < 2; g++) {
                uint32_t off = (uint32_t)((wn * 32 + g * 16 + b_rl) * (LDP * 2)
                                          + ks * 32 + b_cl);
                // NON-trans: W[n][k] k-contiguous is already the "col" B operand.
                ldsm_x4(bh[2 * g][0], bh[2 * g][1], bh[2 * g + 1][0], bh[2 * g + 1][1],
                        wHb + off);
                ldsm_x4(bl[2 * g][0], bl[2 * g][1], bl[2 * g + 1][0], bl[2 * g + 1][1],
                        wLb + off);
            }
#pragma unroll
            for (int hm = 0; hm < 2; hm++)
#pragma unroll
                for (int nb = 0; nb < 4; nb++) {
                    mma_bf16(acc[hm][nb], ah[hm], bh[nb]);
                    mma_bf16(acc[hm][nb], al[hm], bh[nb]);
                    mma_bf16(acc[hm][nb], ah[hm], bl[nb]);
                }
        }
        __syncthreads();
    }

    // ---- epilogue: D frag layout m16n8 (c0,c1 row g; c2,c3 row g+8) ----
#pragma unroll
    for (int hm = 0; hm < 2; hm++)
#pragma unroll
        for (int nb = 0; nb < 4; nb++) {
            int mrow = bm * 128 + wm * 32 + hm * 16 + (l >> 2);
            int ncol = bn * 64 + wn * 32 + nb * 8 + (l & 3) * 2;
            float2 bv = *reinterpret_cast<const float2*>(bias + ncol);
            float2 o0, o1;
            o0.x = acc[hm][nb][0] + bv.x;
            o0.y = acc[hm][nb][1] + bv.y;
            o1.x = acc[hm][nb][2] + bv.x;
            o1.y = acc[hm][nb][3] + bv.y;
            *reinterpret_cast<float2*>(out + (size_t)mrow * 768 + ncol) = o0;
            *reinterpret_cast<float2*>(out + (size_t)(mrow + 8) * 768 + ncol) = o1;
        }
}

// ---------------------------------------------------------------------------
// GRU recurrence — UNCHANGED from R14 (per-source split-phase exchange).
// ---------------------------------------------------------------------------
#define EXG_SRC_BYTES 512

__global__ void __launch_bounds__(256, 1) __cluster_dims__(4, 1, 1)
gru_rec(const float* __restrict__ xg, const float* __restrict__ Whh,
        const float* __restrict__ bhh,
        float* __restrict__ dA, long long sA, int oA,
        float* __restrict__ dB, long long sB, int oB)
{
    __shared__ __align__(16) float sh[3 * 512];   // [3 buf][2 batch][256]
    __shared__ __align__(16) float pr[2][3072];   // [s&1][8 kh][2 batch][192]
    __shared__ __align__(8)  ull  mbx[12];        // [buf][src]

    const int t    = threadIdx.x;
    const int rank = blockIdx.x & 3;
    const int pair = blockIdx.x >> 2;
    const int kh   = t >> 5;
    const int lane = t & 31;
    const int src  = kh >> 1;

    const uint32_t mbbase = smem_u32(mbx);
    const uint32_t shbase = smem_u32(sh);

    ull w2[6][16];
#pragma unroll
    for (int p = 0; p < 6; p++) {
        int r = 6 * lane + p;
        const ull* srcp = reinterpret_cast<const ull*>(
            Whh + (size_t)(((r >> 6) << 8) + (rank << 6) + (r & 63)) * 256 + kh * 32);
#pragma unroll
        for (int kp = 0; kp < 16; kp++)
            w2[p][kp] = srcp[kp];
    }

    for (int i = t; i < 3 * 512; i += 256) sh[i] = 0.f;
    if (t == 0) {
#pragma unroll
        for (int i = 0; i < 12; i++) {
            uint32_t mb = mbbase + i * 8;
            asm volatile("mbarrier.init.shared.b64 [%0], 1;" :: "r"(mb) : "memory");
            asm volatile("mbarrier.arrive.expect_tx.shared.b64 _, [%0], %1;"
                         :: "r"(mb), "r"(EXG_SRC_BYTES) : "memory");
        }
    }
    __syncthreads();
    asm volatile("barrier.cluster.arrive.aligned;" ::: "memory");
    asm volatile("barrier.cluster.wait.aligned;" ::: "memory");

    const int rb = t >> 6;
    const int rj = t & 63;
    const int jg = (rank << 6) + rj;
    const long long bG_r = (long long)pair * 2 + rb;
    float bh0 = 0.f, bh1 = 0.f, bh2 = 0.f;
    const float* xp_base = xg;
    if (t < 128) {
        bh0 = bhh[jg];
        bh1 = bhh[256 + jg];
        bh2 = bhh[512 + jg];
        xp_base = xg + (bG_r << 10) * 768;
    }

    uint32_t ph_bits = 0;
    int cur3 = 0;

    for (int s = 0; s < PS; s++) {
        const int nxt3 = (cur3 == 2) ? 0 : cur3 + 1;
        const int curp = s & 1;

        float xr = 0.f, xz = 0.f, xn = 0.f;
        if (t < 128) {
            const float* xp = xp_base + (size_t)s * 768;
            xr = xp[jg];
            xz = xp[256 + jg];
            xn = xp[512 + jg];
        }

        if (s > 0) {
            uint32_t mb = mbbase + (uint32_t)((cur3 * 4 + src) * 8);
            mb_wait(mb, (ph_bits >> cur3) & 1u);
            ph_bits ^= (1u << cur3);
        }

#pragma unroll
        for (int b = 0; b < 2; b++) {
            ull a0 = 0ull, a1 = 0ull, a2 = 0ull, a3 = 0ull, a4 = 0ull, a5 = 0ull;
            const ulonglong2* h2v =
                reinterpret_cast<const ulonglong2*>(sh + cur3 * 512 + b * 256 + kh * 32);
#pragma unroll
            for (int q = 0; q < 8; q++) {
                ulonglong2 hq = h2v[q];
                fma2(a0, w2[0][2 * q + 0], hq.x); fma2(a1, w2[1][2 * q + 0], hq.x);
                fma2(a2, w2[2][2 * q + 0], hq.x); fma2(a3, w2[3][2 * q + 0], hq.x);
                fma2(a4, w2[4][2 * q + 0], hq.x); fma2(a5, w2[5][2 * q + 0], hq.x);
                fma2(a0, w2[0][2 * q + 1], hq.y); fma2(a1, w2[1][2 * q + 1], hq.y);
                fma2(a2, w2[2][2 * q + 1], hq.y); fma2(a3, w2[3][2 * q + 1], hq.y);
                fma2(a4, w2[4][2 * q + 1], hq.y); fma2(a5, w2[5][2 * q + 1], hq.y);
            }
            float2 u0 = unpack2(a0), u1 = unpack2(a1), u2 = unpack2(a2);
            float2 u3 = unpack2(a3), u4 = unpack2(a4), u5 = unpack2(a5);
            float2* pb = reinterpret_cast<float2*>(
                &pr[curp][kh * 384 + b * 192 + 6 * lane]);
            pb[0] = make_float2(u0.x + u0.y, u1.x + u1.y);
            pb[1] = make_float2(u2.x + u2.y, u3.x + u3.y);
            pb[2] = make_float2(u4.x + u4.y, u5.x + u5.y);
        }
        __syncthreads();

        if (t == 0 && s > 0) {
#pragma unroll
            for (int sp = 0; sp < 4; sp++) {
                uint32_t mb = mbbase + (uint32_t)((cur3 * 4 + sp) * 8);
                asm volatile("mbarrier.arrive.expect_tx.shared.b64 _, [%0], %1;"
                             :: "r"(mb), "r"(EXG_SRC_BYTES) : "memory");
            }
        }

        if (t < 128) {
            float hp = sh[cur3 * 512 + rb * 256 + jg];
            float h0 = bh0, h1 = bh1, h2 = bh2;
#pragma unroll
            for (int q = 0; q < 8; q++) {
                const float* pq = &pr[curp][(q * 2 + rb) * 192];
                h0 += pq[rj];
                h1 += pq[64 + rj];
                h2 += pq[128 + rj];
            }
            float r = 0.5f + 0.5f * tanh_ap(0.5f * (xr + h0));
            float z = 0.5f + 0.5f * tanh_ap(0.5f * (xz + h1));
            float n = tanh_ap(xn + r * h2);
            float hn = (1.f - z) * n + z * hp;

            if (s < PS - 1) {
                uint32_t la  = shbase + (uint32_t)((nxt3 * 512 + rb * 256 + jg) * 4);
                uint32_t lmb = mbbase + (uint32_t)((nxt3 * 4 + rank) * 8);
#pragma unroll
                for (int rr = 0; rr < 4; rr++)
                    st_async_f32(la, lmb, (uint32_t)rr, hn);
            }
            long long row = (bG_r << 10) + s;
            dA[row * sA + oA + jg] = hn;
            dB[row * sB + oB + jg] = hn;
        }
        cur3 = nxt3;
    }

    asm volatile("barrier.cluster.arrive.aligned;" ::: "memory");
    asm volatile("barrier.cluster.wait.aligned;" ::: "memory");
}

// ---------------------------------------------------------------------------
extern "C" void kernel_launch(void* const* d_in, const int* in_sizes, int n_in,
                              void* d_out, int out_size) {
    const float* inp   = (const float*)d_in[0];
    const float* W_ih0 = (const float*)d_in[1];
    const float* W_hh0 = (const float*)d_in[2];
    const float* b_ih0 = (const float*)d_in[3];
    const float* b_hh0 = (const float*)d_in[4];
    const float* W_ih1 = (const float*)d_in[5];
    const float* W_hh1 = (const float*)d_in[6];
    const float* b_ih1 = (const float*)d_in[7];
    const float* b_hh1 = (const float*)d_in[8];
    float* out = (float*)d_out;

    float *xgp = nullptr, *h1p = nullptr;
    __nv_bfloat16 *ahi, *alo, *whi, *wlo;
    cudaGetSymbolAddress((void**)&xgp, g_xg);
    cudaGetSymbolAddress((void**)&h1p, g_h1);
    cudaGetSymbolAddress((void**)&ahi, g_Ahi);
    cudaGetSymbolAddress((void**)&alo, g_Alo);
    cudaGetSymbolAddress((void**)&whi, g_Whi);
    cudaGetSymbolAddress((void**)&wlo, g_Wlo);

    const int nA4 = BSH / 4;          // 4,194,304
    const int nW4 = PG * PH / 4;      // 49,152
    dim3 ggrid(12, 512);

    // Layer 0
    split2<<<nA4 / 256, 256>>>(inp, ahi, alo, nA4);
    split2<<<nW4 / 256, 256>>>(W_ih0, whi, wlo, nW4);
    gemm_mma<<<ggrid, 256>>>(ahi, alo, whi, wlo, b_ih0, xgp);
    gru_rec<<<128, 256>>>(xgp, W_hh0, b_hh0,
                          h1p, 256, 0,
                          out + BSH, 512, 0);
    // Layer 1
    split2<<<nA4 / 256, 256>>>(h1p, ahi, alo, nA4);
    split2<<<nW4 / 256, 256>>>(W_ih1, whi, wlo, nW4);
    gemm_mma<<<ggrid, 256>>>(ahi, alo, whi, wlo, b_ih1, xgp);
    gru_rec<<<128, 256>>>(xgp, W_hh1, b_hh1,
                          out, 256, 0,
                          out + BSH, 512, 256);
}